// round 1
// baseline (speedup 1.0000x reference)
#include <cuda_runtime.h>

#define NNODES 50000
#define NEDGES 800000
#define F_IN   128
#define HID    256
#define NOUT   40

// ---------------- scratch (static device memory, no allocations) ------------
__device__ int   g_cnt[NNODES];
__device__ int   g_off[NNODES + 1];
__device__ int   g_cur[NNODES];
__device__ float g_dinv[NNODES];
__device__ int   g_csrc[NEDGES];
__device__ float g_cw[NEDGES];
__device__ float g_aggx[(size_t)NNODES * F_IN];   // A @ x          (N x 128)
__device__ float g_h1  [(size_t)NNODES * HID];    // relu(.. W1+b1) (N x 256)
__device__ float g_agg1[(size_t)NNODES * HID];    // A @ h1         (N x 256)
__device__ float g_h2  [(size_t)NNODES * HID];    // relu(.. W2+b2) (N x 256)

// ---------------- graph preprocessing ---------------------------------------
__global__ void k_init()
{
    int i = blockIdx.x * blockDim.x + threadIdx.x;
    if (i < NNODES) { g_cnt[i] = 0; g_cur[i] = 0; }
}

__global__ void k_count(const int* __restrict__ ei)
{
    int e = blockIdx.x * blockDim.x + threadIdx.x;
    if (e < NEDGES) atomicAdd(&g_cnt[ei[NEDGES + e]], 1);
}

// single-block exclusive scan over counts; also computes dinv = rsqrt(deg+1)
__global__ void k_scan()
{
    __shared__ int s[1024];
    const int tid = threadIdx.x;
    int carry = 0;
    for (int base = 0; base < NNODES; base += 1024) {
        int i = base + tid;
        int v = (i < NNODES) ? g_cnt[i] : 0;
        if (i < NNODES) g_dinv[i] = rsqrtf((float)(v + 1));  // +1 self loop
        s[tid] = v;
        __syncthreads();
        #pragma unroll
        for (int off = 1; off < 1024; off <<= 1) {
            int t = (tid >= off) ? s[tid - off] : 0;
            __syncthreads();
            s[tid] += t;
            __syncthreads();
        }
        if (i < NNODES) g_off[i] = carry + s[tid] - v;
        carry += s[1023];
        __syncthreads();
    }
    if (tid == 0) g_off[NNODES] = carry;
}

__global__ void k_scatter(const int* __restrict__ ei)
{
    int e = blockIdx.x * blockDim.x + threadIdx.x;
    if (e >= NEDGES) return;
    int s = ei[e];
    int d = ei[NEDGES + e];
    int pos = g_off[d] + atomicAdd(&g_cur[d], 1);
    g_csrc[pos] = s;
    g_cw[pos]   = g_dinv[s] * g_dinv[d];
}

// ---------------- sparse aggregation: warp per destination node --------------
// out[n] = dinv[n]^2 * in[n] + sum_{e: dst=n} w_e * in[src_e]
template <int F>
__device__ __forceinline__ void agg_impl(const float* __restrict__ in,
                                         float* __restrict__ out)
{
    const int warp = (blockIdx.x * blockDim.x + threadIdx.x) >> 5;
    const int lane = threadIdx.x & 31;
    if (warp >= NNODES) return;

    constexpr int V = F / 128;   // float4 chunks per lane
    float4 acc[V];

    const float dn = g_dinv[warp];
    const float w0 = dn * dn;
    const float4* selfrow = (const float4*)(in + (size_t)warp * F);
    #pragma unroll
    for (int v = 0; v < V; v++) {
        float4 t = __ldg(&selfrow[lane + 32 * v]);
        acc[v].x = w0 * t.x; acc[v].y = w0 * t.y;
        acc[v].z = w0 * t.z; acc[v].w = w0 * t.w;
    }

    const int beg = g_off[warp];
    const int end = g_off[warp + 1];
    for (int i = beg; i < end; i++) {
        const int   s = g_csrc[i];
        const float w = g_cw[i];
        const float4* r = (const float4*)(in + (size_t)s * F);
        #pragma unroll
        for (int v = 0; v < V; v++) {
            float4 t = __ldg(&r[lane + 32 * v]);
            acc[v].x += w * t.x; acc[v].y += w * t.y;
            acc[v].z += w * t.z; acc[v].w += w * t.w;
        }
    }

    float4* o = (float4*)(out + (size_t)warp * F);
    #pragma unroll
    for (int v = 0; v < V; v++) o[lane + 32 * v] = acc[v];
}

__global__ void k_agg_x(const float* __restrict__ x) { agg_impl<F_IN>(x, g_aggx); }
__global__ void k_agg_h1()                           { agg_impl<HID>(g_h1, g_agg1); }

// ---------------- dense GEMM + bias + relu (C[MxHID] = A[MxK] @ B[KxHID]) ----
template <int K>
__device__ __forceinline__ void gemm_impl(const float* __restrict__ A,
                                          const float* __restrict__ B,
                                          const float* __restrict__ bias,
                                          float* __restrict__ C)
{
    constexpr int BM = 128, BN = 128, BK = 8;
    __shared__ float As[BK][BM];
    __shared__ float Bs[BK][BN];

    const int tid  = threadIdx.x;          // 256 threads
    const int brow = blockIdx.y * BM;
    const int bcol = blockIdx.x * BN;
    const int tr   = (tid >> 4) * 8;       // 0..120
    const int tc   = (tid & 15) * 8;       // 0..120
    const int arow = tid >> 1;              // 0..127
    const int acol = (tid & 1) * 4;         // 0 or 4
    const int brb  = tid >> 5;              // 0..7
    const int bcb  = (tid & 31) * 4;        // 0..124

    float acc[8][8];
    #pragma unroll
    for (int i = 0; i < 8; i++)
        #pragma unroll
        for (int j = 0; j < 8; j++) acc[i][j] = 0.f;

    const int gr = brow + arow;
    const float* Aptr = A + (size_t)gr * K + acol;

    for (int k0 = 0; k0 < K; k0 += BK) {
        float4 av = make_float4(0.f, 0.f, 0.f, 0.f);
        if (gr < NNODES) av = *(const float4*)(Aptr + k0);
        As[acol + 0][arow] = av.x;
        As[acol + 1][arow] = av.y;
        As[acol + 2][arow] = av.z;
        As[acol + 3][arow] = av.w;

        float4 bv = *(const float4*)(B + (size_t)(k0 + brb) * HID + bcol + bcb);
        *(float4*)(&Bs[brb][bcb]) = bv;
        __syncthreads();

        #pragma unroll
        for (int kk = 0; kk < BK; kk++) {
            float af[8], bf[8];
            *(float4*)(af)     = *(const float4*)(&As[kk][tr]);
            *(float4*)(af + 4) = *(const float4*)(&As[kk][tr + 4]);
            *(float4*)(bf)     = *(const float4*)(&Bs[kk][tc]);
            *(float4*)(bf + 4) = *(const float4*)(&Bs[kk][tc + 4]);
            #pragma unroll
            for (int i = 0; i < 8; i++)
                #pragma unroll
                for (int j = 0; j < 8; j++)
                    acc[i][j] += af[i] * bf[j];
        }
        __syncthreads();
    }

    float bvec[8];
    *(float4*)(bvec)     = *(const float4*)(bias + bcol + tc);
    *(float4*)(bvec + 4) = *(const float4*)(bias + bcol + tc + 4);

    #pragma unroll
    for (int i = 0; i < 8; i++) {
        int row = brow + tr + i;
        if (row < NNODES) {
            float4 o0, o1;
            o0.x = fmaxf(acc[i][0] + bvec[0], 0.f);
            o0.y = fmaxf(acc[i][1] + bvec[1], 0.f);
            o0.z = fmaxf(acc[i][2] + bvec[2], 0.f);
            o0.w = fmaxf(acc[i][3] + bvec[3], 0.f);
            o1.x = fmaxf(acc[i][4] + bvec[4], 0.f);
            o1.y = fmaxf(acc[i][5] + bvec[5], 0.f);
            o1.z = fmaxf(acc[i][6] + bvec[6], 0.f);
            o1.w = fmaxf(acc[i][7] + bvec[7], 0.f);
            *(float4*)(C + (size_t)row * HID + bcol + tc)     = o0;
            *(float4*)(C + (size_t)row * HID + bcol + tc + 4) = o1;
        }
    }
}

__global__ void k_gemm1(const float* __restrict__ W1, const float* __restrict__ b1)
{
    gemm_impl<F_IN>(g_aggx, W1, b1, g_h1);
}
__global__ void k_gemm2(const float* __restrict__ W2, const float* __restrict__ b2)
{
    gemm_impl<HID>(g_agg1, W2, b2, g_h2);
}

// ---------------- classifier: out[Nx40] = h2[Nx256] @ Wc[256x40] + bc --------
__global__ void k_cls(const float* __restrict__ Wc, const float* __restrict__ bc,
                      float* __restrict__ out)
{
    __shared__ float Ws[HID * NOUT];   // 40 KB
    const int tid = threadIdx.x;       // 256
    for (int i = tid; i < HID * NOUT; i += 256) Ws[i] = Wc[i];
    __syncthreads();

    const int row = blockIdx.x * 64 + (tid >> 2);
    const int cg  = (tid & 3) * 10;    // 10 output cols per thread
    if (row >= NNODES) return;

    const float* h = g_h2 + (size_t)row * HID;
    float acc[10];
    #pragma unroll
    for (int j = 0; j < 10; j++) acc[j] = 0.f;

    #pragma unroll 4
    for (int k = 0; k < HID; k++) {
        float hv = __ldg(h + k);
        #pragma unroll
        for (int j = 0; j < 10; j++)
            acc[j] += hv * Ws[k * NOUT + cg + j];
    }
    #pragma unroll
    for (int j = 0; j < 10; j++)
        out[(size_t)row * NOUT + cg + j] = acc[j] + __ldg(bc + cg + j);
}

// ---------------- launch ------------------------------------------------------
extern "C" void kernel_launch(void* const* d_in, const int* in_sizes, int n_in,
                              void* d_out, int out_size)
{
    const float* x   = (const float*)d_in[0];
    const float* W1  = (const float*)d_in[1];
    const float* b1  = (const float*)d_in[2];
    const float* W2  = (const float*)d_in[3];
    const float* b2  = (const float*)d_in[4];
    const float* Wc  = (const float*)d_in[5];
    const float* bc  = (const float*)d_in[6];
    const int*   ei  = (const int*)  d_in[7];
    float*       out = (float*)d_out;

    // --- CSR build ---
    k_init   <<<(NNODES + 255) / 256, 256>>>();
    k_count  <<<(NEDGES + 255) / 256, 256>>>(ei);
    k_scan   <<<1, 1024>>>();
    k_scatter<<<(NEDGES + 255) / 256, 256>>>(ei);

    const int aggBlocks = (NNODES * 32 + 255) / 256;  // warp per node, 8 warps/block
    dim3 gemmGrid(HID / 128, (NNODES + 127) / 128);

    // --- layer 1: agg(x) @ W1 + b1, relu ---
    k_agg_x<<<aggBlocks, 256>>>(x);
    k_gemm1<<<gemmGrid, 256>>>(W1, b1);

    // --- layer 2: agg(h1) @ W2 + b2, relu ---
    k_agg_h1<<<aggBlocks, 256>>>();
    k_gemm2<<<gemmGrid, 256>>>(W2, b2);

    // --- classifier ---
    k_cls<<<(NNODES + 63) / 64, 256>>>(Wc, bc, out);
}

// round 5
// speedup vs baseline: 1.5272x; 1.5272x over previous
#include <cuda_runtime.h>
#include <cuda_bf16.h>
#include <cstdint>

#define NNODES 50000
#define NODPAD 50048
#define NEDGES 800000
#define F_IN   128
#define HID    256
#define NOUT   40
#define K1     (3 * F_IN)   // 384
#define K2     (3 * HID)    // 768
#define MTILES (NODPAD / 128)   // 391

// ---------------- scratch (static device memory, no allocations) ------------
__device__ int   g_cnt[NNODES];
__device__ int   g_off[NNODES];
__device__ int   g_cur[NNODES];
__device__ int   g_total;
__device__ float g_dinv[NNODES];
__device__ int   g_csrc[NEDGES];
__device__ float g_cw[NEDGES];
// concatenated bf16 operands: A' = [hi | lo | hi] along K
__device__ __align__(16) __nv_bfloat16 g_ax_cat[(size_t)NODPAD * K1];
__device__ __align__(16) __nv_bfloat16 g_a1_cat[(size_t)NODPAD * K2];
__device__ __align__(16) float g_h1[(size_t)NNODES * HID];
__device__ __align__(16) float g_h2[(size_t)NNODES * HID];
// weights transposed [n][k'] with segments [hi | hi | lo]
__device__ __align__(16) __nv_bfloat16 g_w1c[HID * K1];
__device__ __align__(16) __nv_bfloat16 g_w2c[HID * K2];

// ---------------- helpers ------------------------------------------------------
__device__ __forceinline__ void split1(float v, __nv_bfloat16& h, __nv_bfloat16& l) {
    h = __float2bfloat16(v);
    l = __float2bfloat16(v - __bfloat162float(h));
}

// split float4 -> packed hi (uint2) and lo (uint2), 4 bf16 each
__device__ __forceinline__ void split4(float4 a, uint2& hi, uint2& lo) {
    __nv_bfloat16 h0, h1, h2, h3, l0, l1, l2, l3;
    split1(a.x, h0, l0); split1(a.y, h1, l1);
    split1(a.z, h2, l2); split1(a.w, h3, l3);
    __nv_bfloat162 hp0 = __halves2bfloat162(h0, h1);
    __nv_bfloat162 hp1 = __halves2bfloat162(h2, h3);
    __nv_bfloat162 lp0 = __halves2bfloat162(l0, l1);
    __nv_bfloat162 lp1 = __halves2bfloat162(l2, l3);
    hi.x = *(uint32_t*)&hp0; hi.y = *(uint32_t*)&hp1;
    lo.x = *(uint32_t*)&lp0; lo.y = *(uint32_t*)&lp1;
}

// ---------------- graph preprocessing ---------------------------------------
__global__ void k_init()
{
    int i = blockIdx.x * blockDim.x + threadIdx.x;
    if (i < NNODES) { g_cnt[i] = 0; g_cur[i] = 0; }
    if (i == 0) g_total = 0;
}

__global__ void k_count(const int* __restrict__ ei)
{
    int e = blockIdx.x * blockDim.x + threadIdx.x;
    if (e < NEDGES) atomicAdd(&g_cnt[ei[NEDGES + e]], 1);
}

__global__ void k_offsets()
{
    int i = blockIdx.x * blockDim.x + threadIdx.x;
    if (i >= NNODES) return;
    int c = g_cnt[i];
    g_off[i]  = atomicAdd(&g_total, c);
    g_dinv[i] = rsqrtf((float)(c + 1));
}

__global__ void k_scatter(const int* __restrict__ ei)
{
    int e = blockIdx.x * blockDim.x + threadIdx.x;
    if (e >= NEDGES) return;
    int s = ei[e];
    int d = ei[NEDGES + e];
    int pos = g_off[d] + atomicAdd(&g_cur[d], 1);
    g_csrc[pos] = s;
    g_cw[pos]   = g_dinv[s] * g_dinv[d];
}

// transpose + split weights into [n][k'] cat layout, segments (hi, hi, lo)
__global__ void k_prepw(const float* __restrict__ W1, const float* __restrict__ W2)
{
    int i = blockIdx.x * blockDim.x + threadIdx.x;
    if (i < HID * K1) {
        int n = i / K1, kp = i % K1;
        int seg = kp / F_IN, k = kp % F_IN;
        __nv_bfloat16 h, l;
        split1(W1[k * HID + n], h, l);
        g_w1c[i] = (seg < 2) ? h : l;
    }
    int j = i - HID * K1;
    if (j >= 0 && j < HID * K2) {
        int n = j / K2, kp = j % K2;
        int seg = kp / HID, k = kp % HID;
        __nv_bfloat16 h, l;
        split1(W2[k * HID + n], h, l);
        g_w2c[j] = (seg < 2) ? h : l;
    }
}

// ---------------- sparse aggregation: warp per destination node --------------
// cat row = [hi | lo | hi] of (dinv^2 * self + sum_e w_e * in[src_e])
template <int F>
__device__ __forceinline__ void agg_impl(const float* __restrict__ in,
                                         __nv_bfloat16* __restrict__ cat)
{
    const int warp = (blockIdx.x * blockDim.x + threadIdx.x) >> 5;
    const int lane = threadIdx.x & 31;
    if (warp >= NNODES) return;

    constexpr int V = F / 128;
    float4 acc[V];

    const float dn = g_dinv[warp];
    const float w0 = dn * dn;
    const float4* selfrow = (const float4*)(in + (size_t)warp * F);
    #pragma unroll
    for (int v = 0; v < V; v++) {
        float4 t = __ldg(&selfrow[lane + 32 * v]);
        acc[v].x = w0 * t.x; acc[v].y = w0 * t.y;
        acc[v].z = w0 * t.z; acc[v].w = w0 * t.w;
    }

    const int beg = g_off[warp];
    const int end = beg + g_cnt[warp];
    for (int i = beg; i < end; i++) {
        const int   s = g_csrc[i];
        const float w = g_cw[i];
        const float4* r = (const float4*)(in + (size_t)s * F);
        #pragma unroll
        for (int v = 0; v < V; v++) {
            float4 t = __ldg(&r[lane + 32 * v]);
            acc[v].x += w * t.x; acc[v].y += w * t.y;
            acc[v].z += w * t.z; acc[v].w += w * t.w;
        }
    }

    __nv_bfloat16* base = cat + (size_t)warp * (3 * F);
    #pragma unroll
    for (int v = 0; v < V; v++) {
        int idx = 4 * (lane + 32 * v);
        uint2 hi, lo;
        split4(acc[v], hi, lo);
        *(uint2*)(base + idx)         = hi;
        *(uint2*)(base + F + idx)     = lo;
        *(uint2*)(base + 2 * F + idx) = hi;
    }
}

__global__ void k_agg_x(const float* __restrict__ x) { agg_impl<F_IN>(x, g_ax_cat); }
__global__ void k_agg_h1()                           { agg_impl<HID>(g_h1, g_a1_cat); }

// ---------------- HMMA bf16 GEMM: C = relu(A' @ B'^T + bias) -----------------
// A': [NODPAD][KCAT] bf16 row-major; B': [HID][KCAT] bf16 row-major (= W^T cat).
// Block 128x128, 8 warps of 64x32, cp.async double-buffered BK=32.
// Fragments via explicit per-thread LDS per the documented m16n8k16 layout.
#define SROW  40   // smem row stride in bf16 elems (32 data + 8 pad = 80 bytes)
#define SROWB 80
#define STAGEE (128 * SROW)
#define STAGEB (128 * SROWB)

template <int KCAT>
__device__ __forceinline__ void gemm_body(const __nv_bfloat16* __restrict__ A,
                                          const __nv_bfloat16* __restrict__ B,
                                          const float* __restrict__ bias,
                                          float* __restrict__ C)
{
    __shared__ __align__(16) __nv_bfloat16 smA[2][STAGEE];
    __shared__ __align__(16) __nv_bfloat16 smB[2][STAGEE];

    const int tid  = threadIdx.x;
    const int lane = tid & 31;
    const int wid  = tid >> 5;
    const int g    = lane >> 2;        // group id 0..7
    const int tg   = lane & 3;         // thread-in-group
    const int wm   = (wid & 1) * 64;   // warp m offset
    const int wn   = (wid >> 1) * 32;  // warp n offset
    const int brow = blockIdx.y * 128;
    const int bcol = blockIdx.x * 128;

    uint32_t sA, sB;
    asm("{ .reg .u64 t; cvta.to.shared.u64 t, %1; cvt.u32.u64 %0, t; }"
        : "=r"(sA) : "l"(&smA[0][0]));
    asm("{ .reg .u64 t; cvta.to.shared.u64 t, %1; cvt.u32.u64 %0, t; }"
        : "=r"(sB) : "l"(&smB[0][0]));

    float acc[4][4][4];
    #pragma unroll
    for (int mi = 0; mi < 4; mi++)
        #pragma unroll
        for (int ni = 0; ni < 4; ni++)
            #pragma unroll
            for (int c = 0; c < 4; c++) acc[mi][ni][c] = 0.f;

    // ---- cp.async stage loader: 128 rows x 64B, 16B per thread x2 ----
    const int lrow = tid >> 2;        // 0..63
    const int lseg = tid & 3;
    auto load_stage = [&](int st, int k0) {
        #pragma unroll
        for (int i = 0; i < 2; i++) {
            int row = lrow + i * 64;
            uint32_t so = (uint32_t)st * STAGEB + row * SROWB + lseg * 16;
            const __nv_bfloat16* ga = A + (size_t)(brow + row) * KCAT + k0 + lseg * 8;
            asm volatile("cp.async.cg.shared.global [%0], [%1], 16;"
                         :: "r"(sA + so), "l"(ga));
            const __nv_bfloat16* gb = B + (size_t)(bcol + row) * KCAT + k0 + lseg * 8;
            asm volatile("cp.async.cg.shared.global [%0], [%1], 16;"
                         :: "r"(sB + so), "l"(gb));
        }
        asm volatile("cp.async.commit_group;");
    };

    constexpr int NK = KCAT / 32;
    load_stage(0, 0);

    for (int ki = 0; ki < NK; ki++) {
        if (ki + 1 < NK) {
            load_stage((ki + 1) & 1, (ki + 1) * 32);
            asm volatile("cp.async.wait_group 1;");
        } else {
            asm volatile("cp.async.wait_group 0;");
        }
        __syncthreads();

        const __nv_bfloat16* bufA = smA[ki & 1];
        const __nv_bfloat16* bufB = smB[ki & 1];

        #pragma unroll
        for (int kk = 0; kk < 2; kk++) {
            const int kbase = kk * 16 + tg * 2;   // element offset in row
            // A frags: a0:(g,k) a1:(g+8,k) a2:(g,k+8) a3:(g+8,k+8)
            uint32_t af[4][4];
            #pragma unroll
            for (int mi = 0; mi < 4; mi++) {
                const __nv_bfloat16* rp0 = bufA + (wm + mi * 16 + g) * SROW + kbase;
                const __nv_bfloat16* rp1 = rp0 + 8 * SROW;
                af[mi][0] = *(const uint32_t*)rp0;
                af[mi][1] = *(const uint32_t*)rp1;
                af[mi][2] = *(const uint32_t*)(rp0 + 8);
                af[mi][3] = *(const uint32_t*)(rp1 + 8);
            }
            // B frags: b0:(n=g, k), b1:(n=g, k+8); smem row index = n
            uint32_t bf[4][2];
            #pragma unroll
            for (int ni = 0; ni < 4; ni++) {
                const __nv_bfloat16* rp = bufB + (wn + ni * 8 + g) * SROW + kbase;
                bf[ni][0] = *(const uint32_t*)rp;
                bf[ni][1] = *(const uint32_t*)(rp + 8);
            }
            #pragma unroll
            for (int mi = 0; mi < 4; mi++)
                #pragma unroll
                for (int ni = 0; ni < 4; ni++) {
                    asm volatile(
                        "mma.sync.aligned.m16n8k16.row.col.f32.bf16.bf16.f32 "
                        "{%0,%1,%2,%3},{%4,%5,%6,%7},{%8,%9},{%0,%1,%2,%3};"
                        : "+f"(acc[mi][ni][0]), "+f"(acc[mi][ni][1]),
                          "+f"(acc[mi][ni][2]), "+f"(acc[mi][ni][3])
                        : "r"(af[mi][0]), "r"(af[mi][1]), "r"(af[mi][2]), "r"(af[mi][3]),
                          "r"(bf[ni][0]), "r"(bf[ni][1]));
                }
        }
        __syncthreads();
    }

    // ---- epilogue: bias + relu. c0,c1:(row g, col tg*2,+1); c2,c3:(row g+8) ----
    #pragma unroll
    for (int ni = 0; ni < 4; ni++) {
        const int col = bcol + wn + ni * 8 + tg * 2;
        const float b0 = __ldg(bias + col);
        const float b1 = __ldg(bias + col + 1);
        #pragma unroll
        for (int mi = 0; mi < 4; mi++) {
            int r0 = brow + wm + mi * 16 + g;
            if (r0 < NNODES) {
                float2 o;
                o.x = fmaxf(acc[mi][ni][0] + b0, 0.f);
                o.y = fmaxf(acc[mi][ni][1] + b1, 0.f);
                *(float2*)(C + (size_t)r0 * HID + col) = o;
            }
            int r1 = r0 + 8;
            if (r1 < NNODES) {
                float2 o;
                o.x = fmaxf(acc[mi][ni][2] + b0, 0.f);
                o.y = fmaxf(acc[mi][ni][3] + b1, 0.f);
                *(float2*)(C + (size_t)r1 * HID + col) = o;
            }
        }
    }
}

// wrappers: bind __device__ globals in DEVICE code (host cannot pass them)
__global__ void __launch_bounds__(256) k_gemm1(const float* __restrict__ b1)
{
    gemm_body<K1>(g_ax_cat, g_w1c, b1, g_h1);
}
__global__ void __launch_bounds__(256) k_gemm2(const float* __restrict__ b2)
{
    gemm_body<K2>(g_a1_cat, g_w2c, b2, g_h2);
}

// ---------------- classifier: out[Nx40] = h2[Nx256] @ Wc[256x40] + bc --------
__global__ void k_cls(const float* __restrict__ Wc, const float* __restrict__ bc,
                      float* __restrict__ out)
{
    __shared__ float Ws[HID * NOUT];   // 40 KB
    const int tid = threadIdx.x;       // 256
    for (int i = tid; i < HID * NOUT; i += 256) Ws[i] = Wc[i];
    __syncthreads();

    const int row = blockIdx.x * 64 + (tid >> 2);
    const int cg  = (tid & 3) * 10;
    if (row >= NNODES) return;

    const float* h = g_h2 + (size_t)row * HID;
    float acc[10];
    #pragma unroll
    for (int j = 0; j < 10; j++) acc[j] = 0.f;

    #pragma unroll 4
    for (int k = 0; k < HID; k++) {
        float hv = __ldg(h + k);
        #pragma unroll
        for (int j = 0; j < 10; j++)
            acc[j] += hv * Ws[k * NOUT + cg + j];
    }
    #pragma unroll
    for (int j = 0; j < 10; j++)
        out[(size_t)row * NOUT + cg + j] = acc[j] + __ldg(bc + cg + j);
}

// ---------------- launch ------------------------------------------------------
extern "C" void kernel_launch(void* const* d_in, const int* in_sizes, int n_in,
                              void* d_out, int out_size)
{
    const float* x   = (const float*)d_in[0];
    const float* W1  = (const float*)d_in[1];
    const float* b1  = (const float*)d_in[2];
    const float* W2  = (const float*)d_in[3];
    const float* b2  = (const float*)d_in[4];
    const float* Wc  = (const float*)d_in[5];
    const float* bc  = (const float*)d_in[6];
    const int*   ei  = (const int*)  d_in[7];
    float*       out = (float*)d_out;

    // --- CSR build (scan-free offsets) ---
    k_init   <<<(NNODES + 255) / 256, 256>>>();
    k_count  <<<(NEDGES + 255) / 256, 256>>>(ei);
    k_offsets<<<(NNODES + 255) / 256, 256>>>();
    k_scatter<<<(NEDGES + 255) / 256, 256>>>(ei);

    // --- weight transpose + bf16 cat split ---
    k_prepw<<<(HID * K1 + HID * K2 + 255) / 256, 256>>>(W1, W2);

    const int aggBlocks = (NNODES * 32 + 255) / 256;
    dim3 gemmGrid(HID / 128, MTILES);

    // --- layer 1: relu(agg(x) @ W1 + b1) ---
    k_agg_x<<<aggBlocks, 256>>>(x);
    k_gemm1<<<gemmGrid, 256>>>(b1);

    // --- layer 2: relu(agg(h1) @ W2 + b2) ---
    k_agg_h1<<<aggBlocks, 256>>>();
    k_gemm2<<<gemmGrid, 256>>>(b2);

    // --- classifier ---
    k_cls<<<(NNODES + 63) / 64, 256>>>(Wc, bc, out);
}

// round 6
// speedup vs baseline: 1.7960x; 1.1760x over previous
#include <cuda_runtime.h>
#include <cuda_bf16.h>
#include <cstdint>

#define NNODES 50000
#define NODPAD 50048
#define NEDGES 800000
#define F_IN   128
#define HID    256
#define NOUT   40
#define MTILES (NODPAD / 128)   // 391

// ---------------- scratch (static device memory, no allocations) ------------
__device__ int   g_cnt[NNODES];
__device__ int   g_off[NNODES];
__device__ int   g_cur[NNODES];
__device__ int   g_total;
__device__ float g_dinv[NNODES];
__device__ int   g_csrc[NEDGES];
__device__ float g_cw[NEDGES];
// hi/lo bf16 split operands (pad rows stay zero: never written)
__device__ __align__(16) __nv_bfloat16 g_ax_hi[(size_t)NODPAD * F_IN];
__device__ __align__(16) __nv_bfloat16 g_ax_lo[(size_t)NODPAD * F_IN];
__device__ __align__(16) __nv_bfloat16 g_a1_hi[(size_t)NODPAD * HID];
__device__ __align__(16) __nv_bfloat16 g_a1_lo[(size_t)NODPAD * HID];
__device__ __align__(16) float g_h1[(size_t)NNODES * HID];
__device__ __align__(16) float g_h2[(size_t)NNODES * HID];
// weights transposed [n][k] K-major, hi/lo
__device__ __align__(16) __nv_bfloat16 g_w1hi[HID * F_IN];
__device__ __align__(16) __nv_bfloat16 g_w1lo[HID * F_IN];
__device__ __align__(16) __nv_bfloat16 g_w2hi[HID * HID];
__device__ __align__(16) __nv_bfloat16 g_w2lo[HID * HID];

// ---------------- helpers ------------------------------------------------------
__device__ __forceinline__ void split1(float v, __nv_bfloat16& h, __nv_bfloat16& l) {
    h = __float2bfloat16(v);
    l = __float2bfloat16(v - __bfloat162float(h));
}

__device__ __forceinline__ void split4(float4 a, uint2& hi, uint2& lo) {
    __nv_bfloat16 h0, h1, h2, h3, l0, l1, l2, l3;
    split1(a.x, h0, l0); split1(a.y, h1, l1);
    split1(a.z, h2, l2); split1(a.w, h3, l3);
    __nv_bfloat162 hp0 = __halves2bfloat162(h0, h1);
    __nv_bfloat162 hp1 = __halves2bfloat162(h2, h3);
    __nv_bfloat162 lp0 = __halves2bfloat162(l0, l1);
    __nv_bfloat162 lp1 = __halves2bfloat162(l2, l3);
    hi.x = *(uint32_t*)&hp0; hi.y = *(uint32_t*)&hp1;
    lo.x = *(uint32_t*)&lp0; lo.y = *(uint32_t*)&lp1;
}

// ---------------- graph preprocessing ---------------------------------------
__global__ void k_init()
{
    int i = blockIdx.x * blockDim.x + threadIdx.x;
    if (i < NNODES) { g_cnt[i] = 0; g_cur[i] = 0; }
    if (i == 0) g_total = 0;
}

__global__ void k_count(const int* __restrict__ ei)
{
    int e = blockIdx.x * blockDim.x + threadIdx.x;
    if (e < NEDGES) atomicAdd(&g_cnt[ei[NEDGES + e]], 1);
}

__global__ void k_offsets()
{
    int i = blockIdx.x * blockDim.x + threadIdx.x;
    if (i >= NNODES) return;
    int c = g_cnt[i];
    g_off[i]  = atomicAdd(&g_total, c);
    g_dinv[i] = rsqrtf((float)(c + 1));
}

__global__ void k_scatter(const int* __restrict__ ei)
{
    int e = blockIdx.x * blockDim.x + threadIdx.x;
    if (e >= NEDGES) return;
    int s = ei[e];
    int d = ei[NEDGES + e];
    int pos = g_off[d] + atomicAdd(&g_cur[d], 1);
    g_csrc[pos] = s;
    g_cw[pos]   = g_dinv[s] * g_dinv[d];
}

// transpose + split weights into [n][k] K-major bf16 hi/lo
__global__ void k_prepw(const float* __restrict__ W1, const float* __restrict__ W2)
{
    int i = blockIdx.x * blockDim.x + threadIdx.x;
    if (i < HID * F_IN) {
        int n = i / F_IN, k = i % F_IN;
        split1(W1[k * HID + n], g_w1hi[i], g_w1lo[i]);
    }
    int j = i - HID * F_IN;
    if (j >= 0 && j < HID * HID) {
        int n = j / HID, k = j % HID;
        split1(W2[k * HID + n], g_w2hi[j], g_w2lo[j]);
    }
}

// ---------------- sparse aggregation: warp per destination node --------------
template <int F>
__device__ __forceinline__ void agg_impl(const float* __restrict__ in,
                                         __nv_bfloat16* __restrict__ ohi,
                                         __nv_bfloat16* __restrict__ olo)
{
    const int warp = (blockIdx.x * blockDim.x + threadIdx.x) >> 5;
    const int lane = threadIdx.x & 31;
    if (warp >= NNODES) return;

    constexpr int V = F / 128;
    float4 acc[V];

    const float dn = g_dinv[warp];
    const float w0 = dn * dn;
    const float4* selfrow = (const float4*)(in + (size_t)warp * F);
    #pragma unroll
    for (int v = 0; v < V; v++) {
        float4 t = __ldg(&selfrow[lane + 32 * v]);
        acc[v].x = w0 * t.x; acc[v].y = w0 * t.y;
        acc[v].z = w0 * t.z; acc[v].w = w0 * t.w;
    }

    const int beg = g_off[warp];
    const int end = beg + g_cnt[warp];
    for (int i = beg; i < end; i++) {
        const int   s = g_csrc[i];
        const float w = g_cw[i];
        const float4* r = (const float4*)(in + (size_t)s * F);
        #pragma unroll
        for (int v = 0; v < V; v++) {
            float4 t = __ldg(&r[lane + 32 * v]);
            acc[v].x += w * t.x; acc[v].y += w * t.y;
            acc[v].z += w * t.z; acc[v].w += w * t.w;
        }
    }

    #pragma unroll
    for (int v = 0; v < V; v++) {
        size_t o = (size_t)warp * F + 4 * (lane + 32 * v);
        uint2 hi, lo;
        split4(acc[v], hi, lo);
        *(uint2*)(ohi + o) = hi;
        *(uint2*)(olo + o) = lo;
    }
}

__global__ void k_agg_x(const float* __restrict__ x) { agg_impl<F_IN>(x, g_ax_hi, g_ax_lo); }
__global__ void k_agg_h1()                           { agg_impl<HID>(g_h1, g_a1_hi, g_a1_lo); }

// ---------------- HMMA bf16 GEMM: C = relu(A' @ B'^T + bias) -----------------
// Virtual K' = 3F with segments A' = [hi|lo|hi], B' = [hi|hi|lo] -> products
// AhBh + AlBh + AhBl in fp32 accumulators (lo*lo dropped, ~2^-16 rel).
// Block 128x128, 8 warps of 64x32, cp.async double-buffered BK=32, ldmatrix frags.
#define SROWB 80   // padded smem row stride (64B data + 16B pad) - conflict-free
#define STAGEB (128 * SROWB)

template <int F>
__device__ __forceinline__ void gemm_body(const __nv_bfloat16* __restrict__ Ahi,
                                          const __nv_bfloat16* __restrict__ Alo,
                                          const __nv_bfloat16* __restrict__ Bhi,
                                          const __nv_bfloat16* __restrict__ Blo,
                                          const float* __restrict__ bias,
                                          float* __restrict__ C)
{
    __shared__ __align__(16) uint8_t smA[2][STAGEB];
    __shared__ __align__(16) uint8_t smB[2][STAGEB];

    const int tid  = threadIdx.x;
    const int lane = tid & 31;
    const int wid  = tid >> 5;
    const int g    = lane >> 2;
    const int tg   = lane & 3;
    const int wm   = (wid & 1) * 64;
    const int wn   = (wid >> 1) * 32;
    const int brow = blockIdx.y * 128;
    const int bcol = blockIdx.x * 128;

    uint32_t sA, sB;
    asm("{ .reg .u64 t; cvta.to.shared.u64 t, %1; cvt.u32.u64 %0, t; }"
        : "=r"(sA) : "l"(&smA[0][0]));
    asm("{ .reg .u64 t; cvta.to.shared.u64 t, %1; cvt.u32.u64 %0, t; }"
        : "=r"(sB) : "l"(&smB[0][0]));

    float acc[4][4][4];
    #pragma unroll
    for (int mi = 0; mi < 4; mi++)
        #pragma unroll
        for (int ni = 0; ni < 4; ni++)
            #pragma unroll
            for (int c = 0; c < 4; c++) acc[mi][ni][c] = 0.f;

    // ---- cp.async stage loader with hi/lo segment selection ----
    const int lrow = tid >> 2;        // 0..63
    const int lseg = tid & 3;
    auto load_stage = [&](int st, int k0) {
        const int seg = k0 / F;                 // 0,1,2
        const int kk0 = k0 - seg * F;
        const __nv_bfloat16* a_src = (seg == 1) ? Alo : Ahi;
        const __nv_bfloat16* b_src = (seg == 2) ? Blo : Bhi;
        #pragma unroll
        for (int i = 0; i < 2; i++) {
            int row = lrow + i * 64;
            uint32_t so = (uint32_t)st * STAGEB + row * SROWB + lseg * 16;
            const __nv_bfloat16* ga = a_src + (size_t)(brow + row) * F + kk0 + lseg * 8;
            asm volatile("cp.async.cg.shared.global [%0], [%1], 16;"
                         :: "r"(sA + so), "l"(ga));
            const __nv_bfloat16* gb = b_src + (size_t)(bcol + row) * F + kk0 + lseg * 8;
            asm volatile("cp.async.cg.shared.global [%0], [%1], 16;"
                         :: "r"(sB + so), "l"(gb));
        }
        asm volatile("cp.async.commit_group;");
    };

    constexpr int NK = 3 * F / 32;
    load_stage(0, 0);

    const int lr  = lane & 15;
    const int lhi = (lane >> 4) * 16;   // byte offset: upper half-warp -> +16B (k+8)

    for (int ki = 0; ki < NK; ki++) {
        if (ki + 1 < NK) {
            load_stage((ki + 1) & 1, (ki + 1) * 32);
            asm volatile("cp.async.wait_group 1;");
        } else {
            asm volatile("cp.async.wait_group 0;");
        }
        __syncthreads();

        const uint32_t bufA = sA + (ki & 1) * STAGEB;
        const uint32_t bufB = sB + (ki & 1) * STAGEB;

        #pragma unroll
        for (int kk = 0; kk < 2; kk++) {
            const uint32_t kb = kk * 32;
            uint32_t af[4][4];
            #pragma unroll
            for (int mi = 0; mi < 4; mi++) {
                uint32_t addr = bufA + (wm + mi * 16 + lr) * SROWB + kb + lhi;
                asm volatile("ldmatrix.sync.aligned.m8n8.x4.shared.b16 {%0,%1,%2,%3}, [%4];"
                             : "=r"(af[mi][0]), "=r"(af[mi][1]),
                               "=r"(af[mi][2]), "=r"(af[mi][3]) : "r"(addr));
            }
            uint32_t bf[4][2];
            #pragma unroll
            for (int p = 0; p < 2; p++) {
                uint32_t r0, r1, r2, r3;
                uint32_t addr = bufB + (wn + p * 16 + lr) * SROWB + kb + lhi;
                asm volatile("ldmatrix.sync.aligned.m8n8.x4.shared.b16 {%0,%1,%2,%3}, [%4];"
                             : "=r"(r0), "=r"(r1), "=r"(r2), "=r"(r3) : "r"(addr));
                bf[2 * p][0]     = r0; bf[2 * p][1]     = r2;
                bf[2 * p + 1][0] = r1; bf[2 * p + 1][1] = r3;
            }
            #pragma unroll
            for (int mi = 0; mi < 4; mi++)
                #pragma unroll
                for (int ni = 0; ni < 4; ni++) {
                    asm volatile(
                        "mma.sync.aligned.m16n8k16.row.col.f32.bf16.bf16.f32 "
                        "{%0,%1,%2,%3},{%4,%5,%6,%7},{%8,%9},{%0,%1,%2,%3};"
                        : "+f"(acc[mi][ni][0]), "+f"(acc[mi][ni][1]),
                          "+f"(acc[mi][ni][2]), "+f"(acc[mi][ni][3])
                        : "r"(af[mi][0]), "r"(af[mi][1]), "r"(af[mi][2]), "r"(af[mi][3]),
                          "r"(bf[ni][0]), "r"(bf[ni][1]));
                }
        }
        __syncthreads();
    }

    // ---- epilogue: bias + relu ----
    #pragma unroll
    for (int ni = 0; ni < 4; ni++) {
        const int col = bcol + wn + ni * 8 + tg * 2;
        const float b0 = __ldg(bias + col);
        const float b1 = __ldg(bias + col + 1);
        #pragma unroll
        for (int mi = 0; mi < 4; mi++) {
            int r0 = brow + wm + mi * 16 + g;
            if (r0 < NNODES) {
                float2 o;
                o.x = fmaxf(acc[mi][ni][0] + b0, 0.f);
                o.y = fmaxf(acc[mi][ni][1] + b1, 0.f);
                *(float2*)(C + (size_t)r0 * HID + col) = o;
            }
            int r1 = r0 + 8;
            if (r1 < NNODES) {
                float2 o;
                o.x = fmaxf(acc[mi][ni][2] + b0, 0.f);
                o.y = fmaxf(acc[mi][ni][3] + b1, 0.f);
                *(float2*)(C + (size_t)r1 * HID + col) = o;
            }
        }
    }
}

__global__ void __launch_bounds__(256) k_gemm1(const float* __restrict__ b1)
{
    gemm_body<F_IN>(g_ax_hi, g_ax_lo, g_w1hi, g_w1lo, b1, g_h1);
}
__global__ void __launch_bounds__(256) k_gemm2(const float* __restrict__ b2)
{
    gemm_body<HID>(g_a1_hi, g_a1_lo, g_w2hi, g_w2lo, b2, g_h2);
}

// ---------------- classifier: out[Nx40] = h2[Nx256] @ Wc[256x40] + bc --------
// 2 rows/thread, float2 weight loads, packed f32x2 FMA.
__global__ void __launch_bounds__(256) k_cls(const float* __restrict__ Wc,
                                             const float* __restrict__ bc,
                                             float* __restrict__ out)
{
    __shared__ float Ws[HID * NOUT];   // 40 KB
    const int tid = threadIdx.x;
    for (int i = tid; i < HID * NOUT; i += 256) Ws[i] = Wc[i];
    __syncthreads();

    const int s  = tid >> 2;                 // 0..63
    const int cg = (tid & 3) * 10;           // col group start (even)
    const int r0 = blockIdx.x * 128 + s;
    const int r1 = r0 + 64;
    const bool v0 = r0 < NNODES;
    const bool v1 = r1 < NNODES;
    if (!v0) return;

    const float* h0 = g_h2 + (size_t)r0 * HID;
    const float* h1 = g_h2 + (size_t)(v1 ? r1 : r0) * HID;

    unsigned long long acc0[5] = {0, 0, 0, 0, 0};
    unsigned long long acc1[5] = {0, 0, 0, 0, 0};

    #pragma unroll 2
    for (int k = 0; k < HID; k += 4) {
        float4 a0 = *(const float4*)(h0 + k);
        float4 a1 = *(const float4*)(h1 + k);
        const float av0[4] = {a0.x, a0.y, a0.z, a0.w};
        const float av1[4] = {a1.x, a1.y, a1.z, a1.w};
        #pragma unroll
        for (int kk = 0; kk < 4; kk++) {
            unsigned long long hb0, hb1;
            asm("mov.b64 %0, {%1, %1};" : "=l"(hb0) : "r"(__float_as_uint(av0[kk])));
            asm("mov.b64 %0, {%1, %1};" : "=l"(hb1) : "r"(__float_as_uint(av1[kk])));
            const float* wrow = Ws + (k + kk) * NOUT + cg;
            #pragma unroll
            for (int j = 0; j < 5; j++) {
                unsigned long long w = *(const unsigned long long*)(wrow + 2 * j);
                asm("fma.rn.f32x2 %0, %1, %2, %0;" : "+l"(acc0[j]) : "l"(hb0), "l"(w));
                asm("fma.rn.f32x2 %0, %1, %2, %0;" : "+l"(acc1[j]) : "l"(hb1), "l"(w));
            }
        }
    }

    #pragma unroll
    for (int j = 0; j < 5; j++) {
        uint32_t lo, hi;
        float bcl = __ldg(bc + cg + 2 * j);
        float bch = __ldg(bc + cg + 2 * j + 1);
        asm("mov.b64 {%0, %1}, %2;" : "=r"(lo), "=r"(hi) : "l"(acc0[j]));
        out[(size_t)r0 * NOUT + cg + 2 * j]     = __uint_as_float(lo) + bcl;
        out[(size_t)r0 * NOUT + cg + 2 * j + 1] = __uint_as_float(hi) + bch;
        if (v1) {
            asm("mov.b64 {%0, %1}, %2;" : "=r"(lo), "=r"(hi) : "l"(acc1[j]));
            out[(size_t)r1 * NOUT + cg + 2 * j]     = __uint_as_float(lo) + bcl;
            out[(size_t)r1 * NOUT + cg + 2 * j + 1] = __uint_as_float(hi) + bch;
        }
    }
}

// ---------------- launch ------------------------------------------------------
extern "C" void kernel_launch(void* const* d_in, const int* in_sizes, int n_in,
                              void* d_out, int out_size)
{
    const float* x   = (const float*)d_in[0];
    const float* W1  = (const float*)d_in[1];
    const float* b1  = (const float*)d_in[2];
    const float* W2  = (const float*)d_in[3];
    const float* b2  = (const float*)d_in[4];
    const float* Wc  = (const float*)d_in[5];
    const float* bc  = (const float*)d_in[6];
    const int*   ei  = (const int*)  d_in[7];
    float*       out = (float*)d_out;

    // --- CSR build (scan-free offsets) ---
    k_init   <<<(NNODES + 255) / 256, 256>>>();
    k_count  <<<(NEDGES + 255) / 256, 256>>>(ei);
    k_offsets<<<(NNODES + 255) / 256, 256>>>();
    k_scatter<<<(NEDGES + 255) / 256, 256>>>(ei);

    // --- weight transpose + bf16 split ---
    k_prepw<<<(HID * F_IN + HID * HID + 255) / 256, 256>>>(W1, W2);

    const int aggBlocks = (NNODES * 32 + 255) / 256;
    dim3 gemmGrid(HID / 128, MTILES);

    // --- layer 1: relu(agg(x) @ W1 + b1) ---
    k_agg_x<<<aggBlocks, 256>>>(x);
    k_gemm1<<<gemmGrid, 256>>>(b1);

    // --- layer 2: relu(agg(h1) @ W2 + b2) ---
    k_agg_h1<<<aggBlocks, 256>>>();
    k_gemm2<<<gemmGrid, 256>>>(b2);

    // --- classifier ---
    k_cls<<<MTILES, 256>>>(Wc, bc, out);
}

// round 7
// speedup vs baseline: 1.7999x; 1.0022x over previous
#include <cuda_runtime.h>
#include <cuda_bf16.h>
#include <cstdint>

#define NNODES 50000
#define NODPAD 50048
#define NEDGES 800000
#define F_IN   128
#define HID    256
#define NOUT   40
#define MTILES (NODPAD / 128)   // 391

// ---------------- scratch (static device memory, no allocations) ------------
__device__ int   g_cnt[NNODES];
__device__ int   g_off[NNODES];
__device__ int   g_cur[NNODES];
__device__ int   g_total;
__device__ float g_dinv[NNODES];
__device__ __align__(8) int2 g_edge[NEDGES];   // (src, weight bits)
// hi/lo bf16 split operands (pad rows stay zero: never written)
__device__ __align__(16) __nv_bfloat16 g_ax_hi[(size_t)NODPAD * F_IN];
__device__ __align__(16) __nv_bfloat16 g_ax_lo[(size_t)NODPAD * F_IN];
__device__ __align__(16) __nv_bfloat16 g_a1_hi[(size_t)NODPAD * HID];
__device__ __align__(16) __nv_bfloat16 g_a1_lo[(size_t)NODPAD * HID];
__device__ __align__(16) float g_h1[(size_t)NNODES * HID];
__device__ __align__(16) float g_h2[(size_t)NNODES * HID];
// weights transposed [n][k] K-major, hi/lo
__device__ __align__(16) __nv_bfloat16 g_w1hi[HID * F_IN];
__device__ __align__(16) __nv_bfloat16 g_w1lo[HID * F_IN];
__device__ __align__(16) __nv_bfloat16 g_w2hi[HID * HID];
__device__ __align__(16) __nv_bfloat16 g_w2lo[HID * HID];

// ---------------- helpers ------------------------------------------------------
__device__ __forceinline__ void split1(float v, __nv_bfloat16& h, __nv_bfloat16& l) {
    h = __float2bfloat16(v);
    l = __float2bfloat16(v - __bfloat162float(h));
}

__device__ __forceinline__ void split4(float4 a, uint2& hi, uint2& lo) {
    __nv_bfloat16 h0, h1, h2, h3, l0, l1, l2, l3;
    split1(a.x, h0, l0); split1(a.y, h1, l1);
    split1(a.z, h2, l2); split1(a.w, h3, l3);
    __nv_bfloat162 hp0 = __halves2bfloat162(h0, h1);
    __nv_bfloat162 hp1 = __halves2bfloat162(h2, h3);
    __nv_bfloat162 lp0 = __halves2bfloat162(l0, l1);
    __nv_bfloat162 lp1 = __halves2bfloat162(l2, l3);
    hi.x = *(uint32_t*)&hp0; hi.y = *(uint32_t*)&hp1;
    lo.x = *(uint32_t*)&lp0; lo.y = *(uint32_t*)&lp1;
}

// ---------------- graph preprocessing ---------------------------------------
__global__ void k_init()
{
    int i = blockIdx.x * blockDim.x + threadIdx.x;
    if (i < NNODES) { g_cnt[i] = 0; g_cur[i] = 0; }
    if (i == 0) g_total = 0;
}

__global__ void k_count(const int* __restrict__ ei)
{
    int e = blockIdx.x * blockDim.x + threadIdx.x;
    if (e < NEDGES) atomicAdd(&g_cnt[ei[NEDGES + e]], 1);
}

__global__ void k_offsets()
{
    int i = blockIdx.x * blockDim.x + threadIdx.x;
    if (i >= NNODES) return;
    int c = g_cnt[i];
    g_off[i]  = atomicAdd(&g_total, c);
    g_dinv[i] = rsqrtf((float)(c + 1));
}

__global__ void k_scatter(const int* __restrict__ ei)
{
    int e = blockIdx.x * blockDim.x + threadIdx.x;
    if (e >= NEDGES) return;
    int s = ei[e];
    int d = ei[NEDGES + e];
    int pos = g_off[d] + atomicAdd(&g_cur[d], 1);
    g_edge[pos] = make_int2(s, __float_as_int(g_dinv[s] * g_dinv[d]));
}

// transpose + split weights into [n][k] K-major bf16 hi/lo
__global__ void k_prepw(const float* __restrict__ W1, const float* __restrict__ W2)
{
    int i = blockIdx.x * blockDim.x + threadIdx.x;
    if (i < HID * F_IN) {
        int n = i / F_IN, k = i % F_IN;
        split1(W1[k * HID + n], g_w1hi[i], g_w1lo[i]);
    }
    int j = i - HID * F_IN;
    if (j >= 0 && j < HID * HID) {
        int n = j / HID, k = j % HID;
        split1(W2[k * HID + n], g_w2hi[j], g_w2lo[j]);
    }
}

// ---------------- sparse aggregation: warp per destination node --------------
template <int F>
__device__ __forceinline__ void agg_impl(const float* __restrict__ in,
                                         __nv_bfloat16* __restrict__ ohi,
                                         __nv_bfloat16* __restrict__ olo)
{
    const int warp = (blockIdx.x * blockDim.x + threadIdx.x) >> 5;
    const int lane = threadIdx.x & 31;
    if (warp >= NNODES) return;

    constexpr int V = F / 128;
    float4 acc[V];

    const float dn = g_dinv[warp];
    const float w0 = dn * dn;
    const float4* selfrow = (const float4*)(in + (size_t)warp * F);
    #pragma unroll
    for (int v = 0; v < V; v++) {
        float4 t = __ldg(&selfrow[lane + 32 * v]);
        acc[v].x = w0 * t.x; acc[v].y = w0 * t.y;
        acc[v].z = w0 * t.z; acc[v].w = w0 * t.w;
    }

    const int beg = g_off[warp];
    const int end = beg + g_cnt[warp];
    int i = beg;
    for (; i + 2 <= end; i += 2) {
        const int2 e0 = g_edge[i];
        const int2 e1 = g_edge[i + 1];
        const float4* r0 = (const float4*)(in + (size_t)e0.x * F);
        const float4* r1 = (const float4*)(in + (size_t)e1.x * F);
        const float we0 = __int_as_float(e0.y);
        const float we1 = __int_as_float(e1.y);
        #pragma unroll
        for (int v = 0; v < V; v++) {
            float4 t0 = __ldg(&r0[lane + 32 * v]);
            float4 t1 = __ldg(&r1[lane + 32 * v]);
            acc[v].x += we0 * t0.x; acc[v].y += we0 * t0.y;
            acc[v].z += we0 * t0.z; acc[v].w += we0 * t0.w;
            acc[v].x += we1 * t1.x; acc[v].y += we1 * t1.y;
            acc[v].z += we1 * t1.z; acc[v].w += we1 * t1.w;
        }
    }
    if (i < end) {
        const int2 e0 = g_edge[i];
        const float4* r0 = (const float4*)(in + (size_t)e0.x * F);
        const float we0 = __int_as_float(e0.y);
        #pragma unroll
        for (int v = 0; v < V; v++) {
            float4 t0 = __ldg(&r0[lane + 32 * v]);
            acc[v].x += we0 * t0.x; acc[v].y += we0 * t0.y;
            acc[v].z += we0 * t0.z; acc[v].w += we0 * t0.w;
        }
    }

    #pragma unroll
    for (int v = 0; v < V; v++) {
        size_t o = (size_t)warp * F + 4 * (lane + 32 * v);
        uint2 hi, lo;
        split4(acc[v], hi, lo);
        *(uint2*)(ohi + o) = hi;
        *(uint2*)(olo + o) = lo;
    }
}

__global__ void k_agg_x(const float* __restrict__ x) { agg_impl<F_IN>(x, g_ax_hi, g_ax_lo); }
__global__ void k_agg_h1()                           { agg_impl<HID>(g_h1, g_a1_hi, g_a1_lo); }

// ---------------- HMMA bf16 GEMM: C = relu(A' @ B'^T + bias) -----------------
// Virtual K' = 3F, A' = [hi|lo|hi], B' = [hi|hi|lo] -> AhBh + AlBh + AhBl.
// Block 128x256 (BN = HID), 8 warps of 64x64, cp.async double-buffered BK=32.
#define SROWB 80               // padded smem row stride, conflict-free for ldmatrix
#define A_STG (128 * SROWB)    // 10240 B
#define B_STG (256 * SROWB)    // 20480 B
#define GEMM_SMEM (2 * A_STG + 2 * B_STG)   // 61440 B (dynamic)

template <int F>
__device__ __forceinline__ void gemm_body(const __nv_bfloat16* __restrict__ Ahi,
                                          const __nv_bfloat16* __restrict__ Alo,
                                          const __nv_bfloat16* __restrict__ Bhi,
                                          const __nv_bfloat16* __restrict__ Blo,
                                          const float* __restrict__ bias,
                                          float* __restrict__ C)
{
    extern __shared__ __align__(16) uint8_t smem_dyn[];
    uint32_t sA;
    asm("{ .reg .u64 t; cvta.to.shared.u64 t, %1; cvt.u32.u64 %0, t; }"
        : "=r"(sA) : "l"(&smem_dyn[0]));
    const uint32_t sB = sA + 2 * A_STG;

    const int tid  = threadIdx.x;
    const int lane = tid & 31;
    const int wid  = tid >> 5;
    const int g    = lane >> 2;
    const int tg   = lane & 3;
    const int wm   = (wid & 1) * 64;
    const int wn   = (wid >> 1) * 64;
    const int brow = blockIdx.x * 128;

    float acc[4][8][4];
    #pragma unroll
    for (int mi = 0; mi < 4; mi++)
        #pragma unroll
        for (int ni = 0; ni < 8; ni++)
            #pragma unroll
            for (int c = 0; c < 4; c++) acc[mi][ni][c] = 0.f;

    // ---- cp.async stage loader ----
    const int lrow = tid >> 2;       // 0..63
    const int lseg = tid & 3;
    auto load_stage = [&](int st, int k0) {
        const int seg = k0 / F;                 // 0,1,2
        const int kk0 = k0 - seg * F;
        const __nv_bfloat16* a_src = (seg == 1) ? Alo : Ahi;
        const __nv_bfloat16* b_src = (seg == 2) ? Blo : Bhi;
        #pragma unroll
        for (int i = 0; i < 2; i++) {           // A: 128 rows
            int row = lrow + i * 64;
            uint32_t so = sA + (uint32_t)st * A_STG + row * SROWB + lseg * 16;
            const __nv_bfloat16* ga = a_src + (size_t)(brow + row) * F + kk0 + lseg * 8;
            asm volatile("cp.async.cg.shared.global [%0], [%1], 16;"
                         :: "r"(so), "l"(ga));
        }
        #pragma unroll
        for (int i = 0; i < 4; i++) {           // B: 256 rows (full HID)
            int row = lrow + i * 64;
            uint32_t so = sB + (uint32_t)st * B_STG + row * SROWB + lseg * 16;
            const __nv_bfloat16* gb = b_src + (size_t)row * F + kk0 + lseg * 8;
            asm volatile("cp.async.cg.shared.global [%0], [%1], 16;"
                         :: "r"(so), "l"(gb));
        }
        asm volatile("cp.async.commit_group;");
    };

    constexpr int NK = 3 * F / 32;
    load_stage(0, 0);

    const int lr  = lane & 15;
    const int lhi = (lane >> 4) * 16;   // +16B: upper half-warp -> k+8

    for (int ki = 0; ki < NK; ki++) {
        if (ki + 1 < NK) {
            load_stage((ki + 1) & 1, (ki + 1) * 32);
            asm volatile("cp.async.wait_group 1;");
        } else {
            asm volatile("cp.async.wait_group 0;");
        }
        __syncthreads();

        const uint32_t bufA = sA + (ki & 1) * A_STG;
        const uint32_t bufB = sB + (ki & 1) * B_STG;

        #pragma unroll
        for (int kk = 0; kk < 2; kk++) {
            const uint32_t kb = kk * 32;
            uint32_t af[4][4];
            #pragma unroll
            for (int mi = 0; mi < 4; mi++) {
                uint32_t addr = bufA + (wm + mi * 16 + lr) * SROWB + kb + lhi;
                asm volatile("ldmatrix.sync.aligned.m8n8.x4.shared.b16 {%0,%1,%2,%3}, [%4];"
                             : "=r"(af[mi][0]), "=r"(af[mi][1]),
                               "=r"(af[mi][2]), "=r"(af[mi][3]) : "r"(addr));
            }
            #pragma unroll
            for (int p = 0; p < 4; p++) {
                uint32_t r0, r1, r2, r3;
                uint32_t addr = bufB + (wn + p * 16 + lr) * SROWB + kb + lhi;
                asm volatile("ldmatrix.sync.aligned.m8n8.x4.shared.b16 {%0,%1,%2,%3}, [%4];"
                             : "=r"(r0), "=r"(r1), "=r"(r2), "=r"(r3) : "r"(addr));
                // ni = 2p : b0=r0, b1=r2 ; ni = 2p+1 : b0=r1, b1=r3
                #pragma unroll
                for (int mi = 0; mi < 4; mi++) {
                    asm volatile(
                        "mma.sync.aligned.m16n8k16.row.col.f32.bf16.bf16.f32 "
                        "{%0,%1,%2,%3},{%4,%5,%6,%7},{%8,%9},{%0,%1,%2,%3};"
                        : "+f"(acc[mi][2 * p][0]), "+f"(acc[mi][2 * p][1]),
                          "+f"(acc[mi][2 * p][2]), "+f"(acc[mi][2 * p][3])
                        : "r"(af[mi][0]), "r"(af[mi][1]), "r"(af[mi][2]), "r"(af[mi][3]),
                          "r"(r0), "r"(r2));
                    asm volatile(
                        "mma.sync.aligned.m16n8k16.row.col.f32.bf16.bf16.f32 "
                        "{%0,%1,%2,%3},{%4,%5,%6,%7},{%8,%9},{%0,%1,%2,%3};"
                        : "+f"(acc[mi][2 * p + 1][0]), "+f"(acc[mi][2 * p + 1][1]),
                          "+f"(acc[mi][2 * p + 1][2]), "+f"(acc[mi][2 * p + 1][3])
                        : "r"(af[mi][0]), "r"(af[mi][1]), "r"(af[mi][2]), "r"(af[mi][3]),
                          "r"(r1), "r"(r3));
                }
            }
        }
        __syncthreads();
    }

    // ---- epilogue: bias + relu ----
    #pragma unroll
    for (int ni = 0; ni < 8; ni++) {
        const int col = wn + ni * 8 + tg * 2;        // global col (bcol = 0)
        const float b0 = __ldg(bias + col);
        const float b1 = __ldg(bias + col + 1);
        #pragma unroll
        for (int mi = 0; mi < 4; mi++) {
            int r0 = brow + wm + mi * 16 + g;
            if (r0 < NNODES) {
                float2 o;
                o.x = fmaxf(acc[mi][ni][0] + b0, 0.f);
                o.y = fmaxf(acc[mi][ni][1] + b1, 0.f);
                *(float2*)(C + (size_t)r0 * HID + col) = o;
            }
            int r1 = r0 + 8;
            if (r1 < NNODES) {
                float2 o;
                o.x = fmaxf(acc[mi][ni][2] + b0, 0.f);
                o.y = fmaxf(acc[mi][ni][3] + b1, 0.f);
                *(float2*)(C + (size_t)r1 * HID + col) = o;
            }
        }
    }
}

__global__ void __launch_bounds__(256) k_gemm1(const float* __restrict__ b1)
{
    gemm_body<F_IN>(g_ax_hi, g_ax_lo, g_w1hi, g_w1lo, b1, g_h1);
}
__global__ void __launch_bounds__(256) k_gemm2(const float* __restrict__ b2)
{
    gemm_body<HID>(g_a1_hi, g_a1_lo, g_w2hi, g_w2lo, b2, g_h2);
}

// ---------------- classifier: out[Nx40] = h2[Nx256] @ Wc[256x40] + bc --------
__global__ void __launch_bounds__(256) k_cls(const float* __restrict__ Wc,
                                             const float* __restrict__ bc,
                                             float* __restrict__ out)
{
    __shared__ float Ws[HID * NOUT];   // 40 KB
    const int tid = threadIdx.x;
    for (int i = tid; i < HID * NOUT; i += 256) Ws[i] = Wc[i];
    __syncthreads();

    const int s  = tid >> 2;                 // 0..63
    const int cg = (tid & 3) * 10;           // col group start (even)
    const int r0 = blockIdx.x * 128 + s;
    const int r1 = r0 + 64;
    const bool v0 = r0 < NNODES;
    const bool v1 = r1 < NNODES;
    if (!v0) return;

    const float* h0 = g_h2 + (size_t)r0 * HID;
    const float* h1 = g_h2 + (size_t)(v1 ? r1 : r0) * HID;

    unsigned long long acc0[5] = {0, 0, 0, 0, 0};
    unsigned long long acc1[5] = {0, 0, 0, 0, 0};

    #pragma unroll 2
    for (int k = 0; k < HID; k += 4) {
        float4 a0 = *(const float4*)(h0 + k);
        float4 a1 = *(const float4*)(h1 + k);
        const float av0[4] = {a0.x, a0.y, a0.z, a0.w};
        const float av1[4] = {a1.x, a1.y, a1.z, a1.w};
        #pragma unroll
        for (int kk = 0; kk < 4; kk++) {
            unsigned long long hb0, hb1;
            asm("mov.b64 %0, {%1, %1};" : "=l"(hb0) : "r"(__float_as_uint(av0[kk])));
            asm("mov.b64 %0, {%1, %1};" : "=l"(hb1) : "r"(__float_as_uint(av1[kk])));
            const float* wrow = Ws + (k + kk) * NOUT + cg;
            #pragma unroll
            for (int j = 0; j < 5; j++) {
                unsigned long long w = *(const unsigned long long*)(wrow + 2 * j);
                asm("fma.rn.f32x2 %0, %1, %2, %0;" : "+l"(acc0[j]) : "l"(hb0), "l"(w));
                asm("fma.rn.f32x2 %0, %1, %2, %0;" : "+l"(acc1[j]) : "l"(hb1), "l"(w));
            }
        }
    }

    #pragma unroll
    for (int j = 0; j < 5; j++) {
        uint32_t lo, hi;
        float bcl = __ldg(bc + cg + 2 * j);
        float bch = __ldg(bc + cg + 2 * j + 1);
        asm("mov.b64 {%0, %1}, %2;" : "=r"(lo), "=r"(hi) : "l"(acc0[j]));
        out[(size_t)r0 * NOUT + cg + 2 * j]     = __uint_as_float(lo) + bcl;
        out[(size_t)r0 * NOUT + cg + 2 * j + 1] = __uint_as_float(hi) + bch;
        if (v1) {
            asm("mov.b64 {%0, %1}, %2;" : "=r"(lo), "=r"(hi) : "l"(acc1[j]));
            out[(size_t)r1 * NOUT + cg + 2 * j]     = __uint_as_float(lo) + bcl;
            out[(size_t)r1 * NOUT + cg + 2 * j + 1] = __uint_as_float(hi) + bch;
        }
    }
}

// ---------------- launch ------------------------------------------------------
extern "C" void kernel_launch(void* const* d_in, const int* in_sizes, int n_in,
                              void* d_out, int out_size)
{
    const float* x   = (const float*)d_in[0];
    const float* W1  = (const float*)d_in[1];
    const float* b1  = (const float*)d_in[2];
    const float* W2  = (const float*)d_in[3];
    const float* b2  = (const float*)d_in[4];
    const float* Wc  = (const float*)d_in[5];
    const float* bc  = (const float*)d_in[6];
    const int*   ei  = (const int*)  d_in[7];
    float*       out = (float*)d_out;

    cudaFuncSetAttribute(k_gemm1, cudaFuncAttributeMaxDynamicSharedMemorySize, GEMM_SMEM);
    cudaFuncSetAttribute(k_gemm2, cudaFuncAttributeMaxDynamicSharedMemorySize, GEMM_SMEM);

    // --- CSR build (scan-free offsets) ---
    k_init   <<<(NNODES + 255) / 256, 256>>>();
    k_count  <<<(NEDGES + 255) / 256, 256>>>(ei);
    k_offsets<<<(NNODES + 255) / 256, 256>>>();
    k_scatter<<<(NEDGES + 255) / 256, 256>>>(ei);

    // --- weight transpose + bf16 split ---
    k_prepw<<<(HID * F_IN + HID * HID + 255) / 256, 256>>>(W1, W2);

    const int aggBlocks = (NNODES * 32 + 255) / 256;

    // --- layer 1: relu(agg(x) @ W1 + b1) ---
    k_agg_x<<<aggBlocks, 256>>>(x);
    k_gemm1<<<MTILES, 256, GEMM_SMEM>>>(b1);

    // --- layer 2: relu(agg(h1) @ W2 + b2) ---
    k_agg_h1<<<aggBlocks, 256>>>();
    k_gemm2<<<MTILES, 256, GEMM_SMEM>>>(b2);

    // --- classifier ---
    k_cls<<<MTILES, 256>>>(Wc, bc, out);
}